// round 1
// baseline (speedup 1.0000x reference)
#include <cuda_runtime.h>
#include <cuda_bf16.h>

// Problem constants
#define BB 2
#define NN 512
#define DD 512
#define FF 64
#define OO 16
#define HH 1024          // H = 2*D? no: H = 2*D = 1024 (ffn hidden)
#define H2 2048          // 2*H (gate+value)
#define CTXD 128
#define FO (FF*OO)       // 1024
#define EPS 1e-5f

// ---------------- scratch (static device globals; no allocation) ----------------
__device__ float g_c[BB][DD];        // 1 + scale
__device__ float g_shift[BB][DD];
__device__ float g_d[BB][H2];
__device__ float g_e[BB][H2];
__device__ float g_Xs[BB][NN][DD];   // x * c
__device__ float g_A[BB][NN][H2];
__device__ float g_AT[BB][H2][NN];
__device__ float g_fbs[BB][FF][DD];  // gathered bias * c
__device__ float g_fbT[BB][DD][FF];  // gathered bias, transposed
__device__ float g_Cf[BB][FF][H2];
__device__ float g_cr[BB][NN][FF];   // raw dot x . bias_f
__device__ float g_Wb[BB][DD][FO];   // gathered out_proj, [d][f*16+o]
__device__ float g_P[BB][NN][FO];    // x @ Wb
__device__ float g_Mm[BB][HH][FO];   // W_out @ Wb
__device__ float g_mx[BB][NN];
__device__ float g_mx2[BB][NN];
__device__ float g_mb[BB][FF];
__device__ float g_mb2[BB][FF];
__device__ float g_Q[BB][FF][OO];

// ---------------- small kernels ----------------

// ss = ctx @ ln_w + ln_b ; c = 1+scale ; shift
__global__ void k_mod(const float* __restrict__ ctx, const float* __restrict__ ln_w,
                      const float* __restrict__ ln_b) {
    int b = blockIdx.x;
    __shared__ float cs[CTXD];
    for (int i = threadIdx.x; i < CTXD; i += blockDim.x) cs[i] = ctx[b * CTXD + i];
    __syncthreads();
    for (int j = threadIdx.x; j < 2 * DD; j += blockDim.x) {
        float s = ln_b[j];
#pragma unroll 4
        for (int k = 0; k < CTXD; k++) s += cs[k] * ln_w[k * (2 * DD) + j];
        if (j < DD) g_c[b][j] = 1.0f + s;
        else        g_shift[b][j - DD] = s;
    }
}

// d = c @ W_in ; e = shift @ W_in + b_in
__global__ void k_de(const float* __restrict__ w_in, const float* __restrict__ b_in) {
    int b = blockIdx.x;
    int j = blockIdx.y * blockDim.x + threadIdx.x;   // < H2
    __shared__ float cs[DD], ss[DD];
    for (int i = threadIdx.x; i < DD; i += blockDim.x) { cs[i] = g_c[b][i]; ss[i] = g_shift[b][i]; }
    __syncthreads();
    float dv = 0.f, ev = 0.f;
#pragma unroll 4
    for (int d = 0; d < DD; d++) {
        float w = w_in[(long)d * H2 + j];
        dv += cs[d] * w;
        ev += ss[d] * w;
    }
    g_d[b][j] = dv;
    g_e[b][j] = ev + b_in[j];
}

// Xs = x * c (per batch column scale)
__global__ void k_scaleX(const float* __restrict__ x) {
    int i = blockIdx.x * blockDim.x + threadIdx.x;
    if (i >= BB * NN * DD) return;
    int d = i % DD;
    int b = i / (NN * DD);
    (&g_Xs[0][0][0])[i] = x[i] * g_c[b][d];
}

// gather feature bias (scaled + transposed), per-(b,f) bias stats, gather out_proj -> Wb
__global__ void k_gather(const int* __restrict__ idx, const float* __restrict__ fb,
                         const float* __restrict__ op) {
    int f = blockIdx.x, b = blockIdx.y;
    int row = idx[b * FF + f];
    const float* src = fb + (long)row * DD;
    float s = 0.f, s2 = 0.f;
    for (int d = threadIdx.x; d < DD; d += blockDim.x) {
        float v = src[d];
        g_fbs[b][f][d] = v * g_c[b][d];
        g_fbT[b][d][f] = v;
        s += v; s2 += v * v;
    }
    __shared__ float r1[256], r2[256];
    r1[threadIdx.x] = s; r2[threadIdx.x] = s2;
    __syncthreads();
    for (int st = 128; st > 0; st >>= 1) {
        if (threadIdx.x < st) { r1[threadIdx.x] += r1[threadIdx.x + st]; r2[threadIdx.x] += r2[threadIdx.x + st]; }
        __syncthreads();
    }
    if (threadIdx.x == 0) { g_mb[b][f] = r1[0] * (1.0f / DD); g_mb2[b][f] = r2[0] * (1.0f / DD); }
    const float* wsrc = op + (long)row * (DD * OO);
    for (int i = threadIdx.x; i < DD * OO; i += blockDim.x) {
        int d = i / OO, o = i % OO;
        g_Wb[b][d][f * OO + o] = wsrc[i];
    }
}

// per-(b,n) x stats
__global__ void k_statsx(const float* __restrict__ x) {
    int n = blockIdx.x, b = blockIdx.y;
    const float* r = x + ((long)b * NN + n) * DD;
    float s = 0.f, s2 = 0.f;
    for (int d = threadIdx.x; d < DD; d += 128) { float v = r[d]; s += v; s2 += v * v; }
    __shared__ float r1[128], r2[128];
    r1[threadIdx.x] = s; r2[threadIdx.x] = s2;
    __syncthreads();
    for (int st = 64; st > 0; st >>= 1) {
        if (threadIdx.x < st) { r1[threadIdx.x] += r1[threadIdx.x + st]; r2[threadIdx.x] += r2[threadIdx.x + st]; }
        __syncthreads();
    }
    if (threadIdx.x == 0) { g_mx[b][n] = r1[0] * (1.0f / DD); g_mx2[b][n] = r2[0] * (1.0f / DD); }
}

// Q[b][f][o] = sum_d b_out[d] * Wb[b][d][f*16+o]
__global__ void k_Q(const float* __restrict__ b_out) {
    int bf = blockIdx.x;
    int b = bf / FF, f = bf % FF;
    int o = threadIdx.x;
    if (o < OO) {
        float s = 0.f;
        for (int d = 0; d < DD; d++) s += b_out[d] * g_Wb[b][d][f * OO + o];
        g_Q[b][f][o] = s;
    }
}

// ---------------- generic tiled SGEMM: C = A(MxK) @ B(KxN), row-major, batched by z ----------------
template <int BM, int BN, int BK, int TM, int TN, int THREADS>
__global__ void sgemm(const float* __restrict__ Ag, const float* __restrict__ Bg,
                      float* __restrict__ Cg, int M, int N, int K,
                      long sA, long sB, long sC) {
    const float* A = Ag + (long)blockIdx.z * sA;
    const float* Bp = Bg + (long)blockIdx.z * sB;
    float* C = Cg + (long)blockIdx.z * sC;
    __shared__ float As[BK][BM + 1];
    __shared__ float Bs[BK][BN];
    int tid = threadIdx.x;
    int tc = tid % (BN / TN);
    int tr = tid / (BN / TN);
    int rowBase = blockIdx.y * BM;
    int colBase = blockIdx.x * BN;
    float acc[TM][TN];
#pragma unroll
    for (int i = 0; i < TM; i++)
#pragma unroll
        for (int j = 0; j < TN; j++) acc[i][j] = 0.f;

    for (int k0 = 0; k0 < K; k0 += BK) {
#pragma unroll
        for (int i = tid; i < BM * BK; i += THREADS) {
            int m = i / BK, kk = i % BK;
            int gr = rowBase + m, gc = k0 + kk;
            As[kk][m] = (gr < M && gc < K) ? A[(long)gr * K + gc] : 0.f;
        }
#pragma unroll
        for (int i = tid; i < BK * BN; i += THREADS) {
            int kk = i / BN, nn = i % BN;
            int gr = k0 + kk, gc = colBase + nn;
            Bs[kk][nn] = (gr < K && gc < N) ? Bp[(long)gr * N + gc] : 0.f;
        }
        __syncthreads();
#pragma unroll
        for (int kk = 0; kk < BK; kk++) {
            float ar[TM], br[TN];
#pragma unroll
            for (int i = 0; i < TM; i++) ar[i] = As[kk][tr * TM + i];
#pragma unroll
            for (int j = 0; j < TN; j++) br[j] = Bs[kk][tc * TN + j];
#pragma unroll
            for (int i = 0; i < TM; i++)
#pragma unroll
                for (int j = 0; j < TN; j++) acc[i][j] += ar[i] * br[j];
        }
        __syncthreads();
    }
#pragma unroll
    for (int i = 0; i < TM; i++) {
        int gr = rowBase + tr * TM + i;
        if (gr < M) {
#pragma unroll
            for (int j = 0; j < TN; j++) {
                int gc = colBase + tc * TN + j;
                if (gc < N) C[(long)gr * N + gc] = acc[i][j];
            }
        }
    }
}

// ---------------- transpose (R x C) -> (C x R), batched by z ----------------
__global__ void k_transpose(const float* __restrict__ in, float* __restrict__ out, int R, int C) {
    __shared__ float t[32][33];
    long boff = (long)blockIdx.z * R * C;
    int c0 = blockIdx.x * 32, r0 = blockIdx.y * 32;
    int x = c0 + threadIdx.x;
#pragma unroll
    for (int i = threadIdx.y; i < 32; i += 8) {
        int y = r0 + i;
        t[i][threadIdx.x] = in[boff + (long)y * C + x];
    }
    __syncthreads();
    int x2 = r0 + threadIdx.x;
#pragma unroll
    for (int i = threadIdx.y; i < 32; i += 8) {
        int y2 = c0 + i;
        out[boff + (long)y2 * R + x2] = t[threadIdx.x][i];
    }
}

// ---------------- fused main kernel ----------------
// block = (n-tile of 128, f, b); one thread per token n. Shared: M_{bf}(64KB), C,d,e (24KB)
__global__ void k_main(float* __restrict__ out) {
    extern __shared__ float sh[];
    float4* M4 = (float4*)sh;                 // HH*OO floats = HH*4 float4
    float* Csh = sh + HH * OO;                // H2
    float* dsh = Csh + H2;                    // H2
    float* esh = dsh + H2;                    // H2

    int b = blockIdx.z, f = blockIdx.y;
    int n0 = blockIdx.x * 128;
    int t = threadIdx.x;

    for (int i = t; i < HH * 4; i += 128) {
        int j = i >> 2, q = i & 3;
        M4[i] = ((const float4*)(&g_Mm[b][j][f * OO]))[q];
    }
    for (int i = t; i < H2; i += 128) {
        Csh[i] = g_Cf[b][f][i];
        dsh[i] = g_d[b][i];
        esh[i] = g_e[b][i];
    }
    __syncthreads();

    int n = n0 + t;
    float mu = g_mx[b][n] + g_mb[b][f];
    float var = g_mx2[b][n] + 2.0f * g_cr[b][n][f] * (1.0f / DD) + g_mb2[b][f] - mu * mu;
    float rs = rsqrtf(var + EPS);

    float acc[OO];
#pragma unroll
    for (int o = 0; o < OO; o++) acc[o] = 0.f;

    const float* ATg = &g_AT[b][0][0] + n;    // stride NN per j

#pragma unroll 4
    for (int j = 0; j < HH; j++) {
        float aG = ATg[(long)j * NN];
        float aV = ATg[(long)(j + HH) * NN];
        float g = fmaf(rs, aG + Csh[j] - mu * dsh[j], esh[j]);
        float v = fmaf(rs, aV + Csh[j + HH] - mu * dsh[j + HH], esh[j + HH]);
        float sg = __fdividef(1.0f, 1.0f + __expf(-g));
        float z = g * sg * v;
        float4 m0 = M4[j * 4 + 0];
        float4 m1 = M4[j * 4 + 1];
        float4 m2 = M4[j * 4 + 2];
        float4 m3 = M4[j * 4 + 3];
        acc[0]  += z * m0.x; acc[1]  += z * m0.y; acc[2]  += z * m0.z; acc[3]  += z * m0.w;
        acc[4]  += z * m1.x; acc[5]  += z * m1.y; acc[6]  += z * m1.z; acc[7]  += z * m1.w;
        acc[8]  += z * m2.x; acc[9]  += z * m2.y; acc[10] += z * m2.z; acc[11] += z * m2.w;
        acc[12] += z * m3.x; acc[13] += z * m3.y; acc[14] += z * m3.z; acc[15] += z * m3.w;
    }

    long ob = (((long)b * NN + n) * FF + f) * OO;
    const float* Pp = &g_P[b][n][f * OO];
#pragma unroll
    for (int o = 0; o < OO; o++) out[ob + o] = acc[o] + Pp[o] + g_Q[b][f][o];
}

// ---------------- launch ----------------
#define SMEM_MAIN ((HH * OO + 3 * H2) * (int)sizeof(float))

extern "C" void kernel_launch(void* const* d_in, const int* in_sizes, int n_in,
                              void* d_out, int out_size) {
    const float* x     = (const float*)d_in[0];
    const int*   idx   = (const int*)d_in[1];
    const float* ctx   = (const float*)d_in[2];
    const float* fb    = (const float*)d_in[3];
    const float* op    = (const float*)d_in[4];
    const float* ln_w  = (const float*)d_in[5];
    const float* ln_b  = (const float*)d_in[6];
    const float* w_in  = (const float*)d_in[7];
    const float* b_in  = (const float*)d_in[8];
    const float* w_out = (const float*)d_in[9];
    const float* b_out = (const float*)d_in[10];
    float* out = (float*)d_out;

    cudaFuncSetAttribute((const void*)k_main, cudaFuncAttributeMaxDynamicSharedMemorySize, SMEM_MAIN);

    float *pXs, *pA, *pAT, *pfbs, *pfbT, *pCf, *pcr, *pWb, *pP, *pM;
    cudaGetSymbolAddress((void**)&pXs,  g_Xs);
    cudaGetSymbolAddress((void**)&pA,   g_A);
    cudaGetSymbolAddress((void**)&pAT,  g_AT);
    cudaGetSymbolAddress((void**)&pfbs, g_fbs);
    cudaGetSymbolAddress((void**)&pfbT, g_fbT);
    cudaGetSymbolAddress((void**)&pCf,  g_Cf);
    cudaGetSymbolAddress((void**)&pcr,  g_cr);
    cudaGetSymbolAddress((void**)&pWb,  g_Wb);
    cudaGetSymbolAddress((void**)&pP,   g_P);
    cudaGetSymbolAddress((void**)&pM,   g_Mm);

    // prep
    k_mod<<<BB, 256>>>(ctx, ln_w, ln_b);
    k_scaleX<<<(BB * NN * DD) / 256, 256>>>(x);
    k_gather<<<dim3(FF, BB), 256>>>(idx, fb, op);
    k_de<<<dim3(BB, H2 / 256), 256>>>(w_in, b_in);
    k_statsx<<<dim3(NN, BB), 128>>>(x);
    k_Q<<<BB * FF, 32>>>(b_out);

    // GEMMs: C = A @ B
    // A_full = Xs @ W_in   (512 x 2048, K=512) per batch
    sgemm<128, 128, 8, 8, 8, 256><<<dim3(H2 / 128, NN / 128, BB), 256>>>(
        pXs, w_in, pA, NN, H2, DD, (long)NN * DD, 0, (long)NN * H2);
    // transpose A -> AT
    k_transpose<<<dim3(H2 / 32, NN / 32, BB), dim3(32, 8)>>>(pA, pAT, NN, H2);
    // Cf = fbs @ W_in   (64 x 2048, K=512)
    sgemm<128, 128, 8, 8, 8, 256><<<dim3(H2 / 128, 1, BB), 256>>>(
        pfbs, w_in, pCf, FF, H2, DD, (long)FF * DD, 0, (long)FF * H2);
    // cr = X @ fbT      (512 x 64, K=512)
    sgemm<128, 128, 8, 8, 8, 256><<<dim3(1, NN / 128, BB), 256>>>(
        x, pfbT, pcr, NN, FF, DD, (long)NN * DD, (long)DD * FF, (long)NN * FF);
    // P = X @ Wb        (512 x 1024, K=512)
    sgemm<128, 128, 8, 8, 8, 256><<<dim3(FO / 128, NN / 128, BB), 256>>>(
        x, pWb, pP, NN, FO, DD, (long)NN * DD, (long)DD * FO, (long)NN * FO);
    // Mm = W_out @ Wb   (1024 x 1024, K=512)
    sgemm<128, 128, 8, 8, 8, 256><<<dim3(FO / 128, HH / 128, BB), 256>>>(
        w_out, pWb, pM, HH, FO, DD, 0, (long)DD * FO, (long)HH * FO);

    // fused main
    k_main<<<dim3(NN / 128, FF, BB), 128, SMEM_MAIN>>>(out);
}

// round 2
// speedup vs baseline: 2.7361x; 2.7361x over previous
#include <cuda_runtime.h>
#include <cuda_bf16.h>

// Problem constants
#define BB 2
#define NN 512
#define DD 512
#define FF 64
#define OO 16
#define HH 1024          // ffn hidden H
#define H2 2048          // 2*H (gate+value)
#define CTXD 128
#define FO (FF*OO)       // 1024
#define FBM 66           // fbs rows: 64 features + c + shift
#define EPS 1e-5f

// ---------------- scratch (static device globals; no allocation) ----------------
__device__ float g_c[BB][DD];          // 1 + scale
__device__ float g_Xs[BB][NN][DD];     // x * c
__device__ float g_A[BB][NN][H2];
__device__ float g_AT[BB][H2][NN];
__device__ float g_fbs[BB][FBM][DD];   // rows 0..63: gathered bias*c; row 64: c; row 65: shift
__device__ float g_fbT[BB][DD][FF];    // gathered bias, transposed (raw)
__device__ float g_Cf[BB][FBM][H2];    // rows 0..63: Cf; row 64: d; row 65: e_raw
__device__ float g_cr[BB][NN][FF];     // raw dot x . bias_f
__device__ float g_Wb[BB][DD][FO];     // gathered out_proj, [d][f*16+o]
__device__ float g_P[BB][NN][FO];      // x @ Wb
__device__ float g_Mm[BB][HH][FO];     // W_out @ Wb
__device__ float g_mx[BB][NN];
__device__ float g_mx2[BB][NN];
__device__ float g_mb[BB][FF];
__device__ float g_mb2[BB][FF];
__device__ float g_Q[BB][FF][OO];

// ---------------- small kernels ----------------

// ss = ctx @ ln_w + ln_b ; writes c (and into fbs row 64), shift (fbs row 65)
__global__ void k_mod(const float* __restrict__ ctx, const float* __restrict__ ln_w,
                      const float* __restrict__ ln_b) {
    int b = blockIdx.x;
    int j = blockIdx.y * 128 + threadIdx.x;
    __shared__ float cs[CTXD];
    cs[threadIdx.x] = ctx[b * CTXD + threadIdx.x];
    __syncthreads();
    float s = ln_b[j];
#pragma unroll 8
    for (int k = 0; k < CTXD; k++) s += cs[k] * ln_w[k * (2 * DD) + j];
    if (j < DD) {
        g_c[b][j] = 1.0f + s;
        g_fbs[b][64][j] = 1.0f + s;
    } else {
        g_fbs[b][65][j - DD] = s;
    }
}

// per-(b,n): Xs = x*c, and row stats of x
__global__ void k_xprep(const float* __restrict__ x) {
    int n = blockIdx.x, b = blockIdx.y;
    int t = threadIdx.x;  // 128 threads, 512 floats/row
    const float4* r = (const float4*)(x + ((long)b * NN + n) * DD);
    const float4* c4 = (const float4*)(&g_c[b][0]);
    float4* w = (float4*)(&g_Xs[b][n][0]);
    float4 v = r[t];
    float4 cc = c4[t];
    w[t] = make_float4(v.x * cc.x, v.y * cc.y, v.z * cc.z, v.w * cc.w);
    float s = v.x + v.y + v.z + v.w;
    float s2 = v.x * v.x + v.y * v.y + v.z * v.z + v.w * v.w;
#pragma unroll
    for (int o = 16; o > 0; o >>= 1) {
        s  += __shfl_xor_sync(0xffffffffu, s, o);
        s2 += __shfl_xor_sync(0xffffffffu, s2, o);
    }
    __shared__ float r1[4], r2[4];
    if ((t & 31) == 0) { r1[t >> 5] = s; r2[t >> 5] = s2; }
    __syncthreads();
    if (t == 0) {
        float a = r1[0] + r1[1] + r1[2] + r1[3];
        float a2 = r2[0] + r2[1] + r2[2] + r2[3];
        g_mx[b][n] = a * (1.0f / DD);
        g_mx2[b][n] = a2 * (1.0f / DD);
    }
}

// gather feature bias (scaled + transposed), bias stats, gather out_proj -> Wb, and Q epilogue
__global__ void k_gather(const int* __restrict__ idx, const float* __restrict__ fb,
                         const float* __restrict__ op, const float* __restrict__ b_out) {
    int f = blockIdx.x, b = blockIdx.y;
    int tid = threadIdx.x;  // 256
    int row = idx[b * FF + f];
    const float* src = fb + (long)row * DD;
    float s = 0.f, s2 = 0.f;
    for (int d = tid; d < DD; d += 256) {
        float v = src[d];
        g_fbs[b][f][d] = v * g_c[b][d];
        g_fbT[b][d][f] = v;
        s += v; s2 += v * v;
    }
#pragma unroll
    for (int o = 16; o > 0; o >>= 1) {
        s  += __shfl_xor_sync(0xffffffffu, s, o);
        s2 += __shfl_xor_sync(0xffffffffu, s2, o);
    }
    __shared__ float r1[8], r2[8];
    if ((tid & 31) == 0) { r1[tid >> 5] = s; r2[tid >> 5] = s2; }
    __syncthreads();
    if (tid == 0) {
        float a = 0.f, a2 = 0.f;
#pragma unroll
        for (int i = 0; i < 8; i++) { a += r1[i]; a2 += r2[i]; }
        g_mb[b][f] = a * (1.0f / DD);
        g_mb2[b][f] = a2 * (1.0f / DD);
    }
    const float* wsrc = op + (long)row * (DD * OO);
    for (int i = tid; i < DD * OO; i += 256) {
        int d = i / OO, o = i % OO;
        g_Wb[b][d][f * OO + o] = wsrc[i];
    }
    // Q[b][f][o] = sum_d b_out[d] * wsrc[d*16+o]
    int o = tid & 15, c = tid >> 4;   // 16 chunks x 16 o
    float q = 0.f;
#pragma unroll 4
    for (int i = 0; i < DD / 16; i++) {
        int d = c * (DD / 16) + i;
        q += b_out[d] * wsrc[d * OO + o];
    }
    __shared__ float qs[16][17];
    qs[c][o] = q;
    __syncthreads();
    if (c == 0) {
        float a = 0.f;
#pragma unroll
        for (int i = 0; i < 16; i++) a += qs[i][o];
        g_Q[b][f][o] = a;
    }
}

// ---------------- tiled SGEMM: C = A(MxK) @ B(KxN), row-major, batched by z ----------------
// K % 16 == 0, N % BN == 0 (or at least colBase+BN <= N), float4-aligned pointers.
template <int BM, int BN, int BK, int TM, int TN, int THREADS>
__global__ void __launch_bounds__(THREADS) sgemm(
        const float* __restrict__ Ag, const float* __restrict__ Bg,
        float* __restrict__ Cg, int M, int N, int K,
        long sA, long sB, long sC) {
    const float* A = Ag + (long)blockIdx.z * sA;
    const float* Bp = Bg + (long)blockIdx.z * sB;
    float* C = Cg + (long)blockIdx.z * sC;
    __shared__ float As[BK][BM + 4];
    __shared__ float Bs[BK][BN];
    constexpr int KQ = BK / 4;
    constexpr int N4 = BN / 4;
    constexpr int A4 = BM * KQ;
    constexpr int B4 = BK * N4;
    int tid = threadIdx.x;
    int tc = tid % (BN / TN);
    int tr = tid / (BN / TN);
    int rowBase = blockIdx.y * BM;
    int colBase = blockIdx.x * BN;
    float acc[TM][TN];
#pragma unroll
    for (int i = 0; i < TM; i++)
#pragma unroll
        for (int j = 0; j < TN; j++) acc[i][j] = 0.f;

    for (int k0 = 0; k0 < K; k0 += BK) {
#pragma unroll
        for (int fi = tid; fi < A4; fi += THREADS) {
            int m = fi / KQ, k = (fi % KQ) * 4;
            int gr = rowBase + m;
            float4 v = make_float4(0.f, 0.f, 0.f, 0.f);
            if (gr < M) v = *(const float4*)&A[(long)gr * K + k0 + k];
            As[k + 0][m] = v.x; As[k + 1][m] = v.y; As[k + 2][m] = v.z; As[k + 3][m] = v.w;
        }
#pragma unroll
        for (int fi = tid; fi < B4; fi += THREADS) {
            int kk = fi / N4, nn = (fi % N4) * 4;
            *(float4*)&Bs[kk][nn] = *(const float4*)&Bp[(long)(k0 + kk) * N + colBase + nn];
        }
        __syncthreads();
#pragma unroll
        for (int kk = 0; kk < BK; kk++) {
            float ar[TM], br[TN];
#pragma unroll
            for (int i = 0; i < TM; i += 4)
                *(float4*)&ar[i] = *(const float4*)&As[kk][tr * TM + i];
#pragma unroll
            for (int j = 0; j < TN; j += 4)
                *(float4*)&br[j] = *(const float4*)&Bs[kk][tc * TN + j];
#pragma unroll
            for (int i = 0; i < TM; i++)
#pragma unroll
                for (int j = 0; j < TN; j++) acc[i][j] = fmaf(ar[i], br[j], acc[i][j]);
        }
        __syncthreads();
    }
#pragma unroll
    for (int i = 0; i < TM; i++) {
        int gr = rowBase + tr * TM + i;
        if (gr < M) {
#pragma unroll
            for (int j = 0; j < TN; j += 4) {
                float4 v = make_float4(acc[i][j], acc[i][j + 1], acc[i][j + 2], acc[i][j + 3]);
                *(float4*)&C[(long)gr * N + colBase + tc * TN + j] = v;
            }
        }
    }
}

// ---------------- transpose (R x C) -> (C x R), batched by z ----------------
__global__ void k_transpose(const float* __restrict__ in, float* __restrict__ out, int R, int C) {
    __shared__ float t[32][33];
    long boff = (long)blockIdx.z * R * C;
    int c0 = blockIdx.x * 32, r0 = blockIdx.y * 32;
    int x = c0 + threadIdx.x;
#pragma unroll
    for (int i = threadIdx.y; i < 32; i += 8) {
        int y = r0 + i;
        t[i][threadIdx.x] = in[boff + (long)y * C + x];
    }
    __syncthreads();
    int x2 = r0 + threadIdx.x;
#pragma unroll
    for (int i = threadIdx.y; i < 32; i += 8) {
        int y2 = c0 + i;
        out[boff + (long)y2 * R + x2] = t[threadIdx.x][i];
    }
}

// ---------------- fused main kernel ----------------
// block = (n-tile of 256, f, b); one thread per token. Shared: M_{bf}(64KB), C,d,e (24KB)
__global__ void __launch_bounds__(256) k_main(float* __restrict__ out,
                                              const float* __restrict__ b_in) {
    extern __shared__ float sh[];
    float4* M4 = (float4*)sh;                 // HH*OO floats = HH*4 float4
    float* Csh = sh + HH * OO;                // H2
    float* dsh = Csh + H2;                    // H2
    float* esh = dsh + H2;                    // H2

    int b = blockIdx.z, f = blockIdx.y;
    int n0 = blockIdx.x * 256;
    int t = threadIdx.x;

    for (int i = t; i < HH * 4; i += 256) {
        int j = i >> 2, q = i & 3;
        M4[i] = ((const float4*)(&g_Mm[b][j][f * OO]))[q];
    }
    for (int i = t; i < H2; i += 256) {
        Csh[i] = g_Cf[b][f][i];
        dsh[i] = g_Cf[b][64][i];
        esh[i] = g_Cf[b][65][i] + b_in[i];
    }
    __syncthreads();

    int n = n0 + t;
    float mu = g_mx[b][n] + g_mb[b][f];
    float var = g_mx2[b][n] + 2.0f * g_cr[b][n][f] * (1.0f / DD) + g_mb2[b][f] - mu * mu;
    float rs = rsqrtf(var + EPS);

    float acc[OO];
#pragma unroll
    for (int o = 0; o < OO; o++) acc[o] = 0.f;

    const float* ATg = &g_AT[b][0][0] + n;    // stride NN per j

#pragma unroll 4
    for (int j = 0; j < HH; j++) {
        float aG = ATg[(long)j * NN];
        float aV = ATg[(long)(j + HH) * NN];
        float g = fmaf(rs, aG + Csh[j] - mu * dsh[j], esh[j]);
        float v = fmaf(rs, aV + Csh[j + HH] - mu * dsh[j + HH], esh[j + HH]);
        float sg = __fdividef(1.0f, 1.0f + __expf(-g));
        float z = g * sg * v;
        float4 m0 = M4[j * 4 + 0];
        float4 m1 = M4[j * 4 + 1];
        float4 m2 = M4[j * 4 + 2];
        float4 m3 = M4[j * 4 + 3];
        acc[0]  += z * m0.x; acc[1]  += z * m0.y; acc[2]  += z * m0.z; acc[3]  += z * m0.w;
        acc[4]  += z * m1.x; acc[5]  += z * m1.y; acc[6]  += z * m1.z; acc[7]  += z * m1.w;
        acc[8]  += z * m2.x; acc[9]  += z * m2.y; acc[10] += z * m2.z; acc[11] += z * m2.w;
        acc[12] += z * m3.x; acc[13] += z * m3.y; acc[14] += z * m3.z; acc[15] += z * m3.w;
    }

    long ob = (((long)b * NN + n) * FF + f) * OO;
    const float* Pp = &g_P[b][n][f * OO];
#pragma unroll
    for (int o = 0; o < OO; o++) out[ob + o] = acc[o] + Pp[o] + g_Q[b][f][o];
}

// ---------------- launch ----------------
#define SMEM_MAIN ((HH * OO + 3 * H2) * (int)sizeof(float))

extern "C" void kernel_launch(void* const* d_in, const int* in_sizes, int n_in,
                              void* d_out, int out_size) {
    const float* x     = (const float*)d_in[0];
    const int*   idx   = (const int*)d_in[1];
    const float* ctx   = (const float*)d_in[2];
    const float* fb    = (const float*)d_in[3];
    const float* op    = (const float*)d_in[4];
    const float* ln_w  = (const float*)d_in[5];
    const float* ln_b  = (const float*)d_in[6];
    const float* w_in  = (const float*)d_in[7];
    const float* b_in  = (const float*)d_in[8];
    const float* w_out = (const float*)d_in[9];
    const float* b_out = (const float*)d_in[10];
    float* out = (float*)d_out;

    static bool attr_set = false;
    if (!attr_set) {
        cudaFuncSetAttribute((const void*)k_main, cudaFuncAttributeMaxDynamicSharedMemorySize, SMEM_MAIN);
        attr_set = true;
    }

    float *pXs, *pA, *pAT, *pfbs, *pfbT, *pCf, *pcr, *pWb, *pP, *pM;
    cudaGetSymbolAddress((void**)&pXs,  g_Xs);
    cudaGetSymbolAddress((void**)&pA,   g_A);
    cudaGetSymbolAddress((void**)&pAT,  g_AT);
    cudaGetSymbolAddress((void**)&pfbs, g_fbs);
    cudaGetSymbolAddress((void**)&pfbT, g_fbT);
    cudaGetSymbolAddress((void**)&pCf,  g_Cf);
    cudaGetSymbolAddress((void**)&pcr,  g_cr);
    cudaGetSymbolAddress((void**)&pWb,  g_Wb);
    cudaGetSymbolAddress((void**)&pP,   g_P);
    cudaGetSymbolAddress((void**)&pM,   g_Mm);

    // prep
    k_mod<<<dim3(BB, (2 * DD) / 128), 128>>>(ctx, ln_w, ln_b);
    k_xprep<<<dim3(NN, BB), 128>>>(x);
    k_gather<<<dim3(FF, BB), 256>>>(idx, fb, op, b_out);

    // GEMMs: C = A @ B
    // A_full = Xs @ W_in   (512 x 2048, K=512) per batch
    sgemm<128, 128, 16, 8, 8, 256><<<dim3(H2 / 128, NN / 128, BB), 256>>>(
        pXs, w_in, pA, NN, H2, DD, (long)NN * DD, 0, (long)NN * H2);
    // transpose A -> AT
    k_transpose<<<dim3(H2 / 32, NN / 32, BB), dim3(32, 8)>>>(pA, pAT, NN, H2);
    // Cf_ext = fbs_ext @ W_in   (66 x 2048, K=512); rows 64/65 produce d and e_raw
    sgemm<128, 128, 16, 8, 8, 256><<<dim3(H2 / 128, 1, BB), 256>>>(
        pfbs, w_in, pCf, FBM, H2, DD, (long)FBM * DD, 0, (long)FBM * H2);
    // cr = X @ fbT      (512 x 64, K=512)
    sgemm<64, 64, 16, 4, 4, 256><<<dim3(1, NN / 64, BB), 256>>>(
        x, pfbT, pcr, NN, FF, DD, (long)NN * DD, (long)DD * FF, (long)NN * FF);
    // P = X @ Wb        (512 x 1024, K=512)
    sgemm<128, 64, 16, 8, 4, 256><<<dim3(FO / 64, NN / 128, BB), 256>>>(
        x, pWb, pP, NN, FO, DD, (long)NN * DD, (long)DD * FO, (long)NN * FO);
    // Mm = W_out @ Wb   (1024 x 1024, K=512)
    sgemm<128, 128, 16, 8, 8, 256><<<dim3(FO / 128, HH / 128, BB), 256>>>(
        w_out, pWb, pM, HH, FO, DD, 0, (long)DD * FO, (long)HH * FO);

    // fused main
    k_main<<<dim3(NN / 256, FF, BB), 256, SMEM_MAIN>>>(out, b_in);
}

// round 3
// speedup vs baseline: 2.7363x; 1.0001x over previous
#include <cuda_runtime.h>
#include <cuda_bf16.h>

// Problem constants
#define BB 2
#define NN 512
#define DD 512
#define FF 64
#define OO 16
#define HH 1024          // ffn hidden H
#define H2 2048          // 2*H (gate+value)
#define CTXD 128
#define FO (FF*OO)       // 1024
#define FBM 66           // fbs rows: 64 features + c + shift
#define EPS 1e-5f

// ---------------- scratch (static device globals; no allocation) ----------------
__device__ float g_c[BB][DD];          // 1 + scale
__device__ float g_Xs[BB][NN][DD];     // x * c
__device__ float g_A[BB][NN][H2];
__device__ float g_AT[BB][H2][NN];
__device__ float g_fbs[BB][FBM][DD];   // rows 0..63: gathered bias*c; row 64: c; row 65: shift
__device__ float g_fbT[BB][DD][FF];    // gathered bias, transposed (raw)
__device__ float g_Cf[BB][FBM][H2];    // rows 0..63: Cf; row 64: d; row 65: e_raw
__device__ float g_cr[BB][NN][FF];     // raw dot x . bias_f
__device__ float g_Wb[BB][DD][FO];     // gathered out_proj, [d][f*16+o]
__device__ float g_P[BB][NN][FO];      // x @ Wb
__device__ float g_Mm[BB][HH][FO];     // W_out @ Wb
__device__ float g_mx[BB][NN];
__device__ float g_mx2[BB][NN];
__device__ float g_mb[BB][FF];
__device__ float g_mb2[BB][FF];
__device__ float g_Q[BB][FF][OO];

// ---------------- small kernels ----------------

// ss = ctx @ ln_w + ln_b ; writes c (and into fbs row 64), shift (fbs row 65)
__global__ void k_mod(const float* __restrict__ ctx, const float* __restrict__ ln_w,
                      const float* __restrict__ ln_b) {
    int b = blockIdx.x;
    int j = blockIdx.y * 128 + threadIdx.x;
    __shared__ float cs[CTXD];
    cs[threadIdx.x] = ctx[b * CTXD + threadIdx.x];
    __syncthreads();
    float s = ln_b[j];
#pragma unroll 8
    for (int k = 0; k < CTXD; k++) s += cs[k] * ln_w[k * (2 * DD) + j];
    if (j < DD) {
        g_c[b][j] = 1.0f + s;
        g_fbs[b][64][j] = 1.0f + s;
    } else {
        g_fbs[b][65][j - DD] = s;
    }
}

// per-(b,n): Xs = x*c, and row stats of x
__global__ void k_xprep(const float* __restrict__ x) {
    int n = blockIdx.x, b = blockIdx.y;
    int t = threadIdx.x;  // 128 threads, 512 floats/row
    const float4* r = (const float4*)(x + ((long)b * NN + n) * DD);
    const float4* c4 = (const float4*)(&g_c[b][0]);
    float4* w = (float4*)(&g_Xs[b][n][0]);
    float4 v = r[t];
    float4 cc = c4[t];
    w[t] = make_float4(v.x * cc.x, v.y * cc.y, v.z * cc.z, v.w * cc.w);
    float s = v.x + v.y + v.z + v.w;
    float s2 = v.x * v.x + v.y * v.y + v.z * v.z + v.w * v.w;
#pragma unroll
    for (int o = 16; o > 0; o >>= 1) {
        s  += __shfl_xor_sync(0xffffffffu, s, o);
        s2 += __shfl_xor_sync(0xffffffffu, s2, o);
    }
    __shared__ float r1[4], r2[4];
    if ((t & 31) == 0) { r1[t >> 5] = s; r2[t >> 5] = s2; }
    __syncthreads();
    if (t == 0) {
        float a = r1[0] + r1[1] + r1[2] + r1[3];
        float a2 = r2[0] + r2[1] + r2[2] + r2[3];
        g_mx[b][n] = a * (1.0f / DD);
        g_mx2[b][n] = a2 * (1.0f / DD);
    }
}

// gather feature bias (scaled + transposed), bias stats, gather out_proj -> Wb, and Q epilogue
__global__ void k_gather(const int* __restrict__ idx, const float* __restrict__ fb,
                         const float* __restrict__ op, const float* __restrict__ b_out) {
    int f = blockIdx.x, b = blockIdx.y;
    int tid = threadIdx.x;  // 256
    int row = idx[b * FF + f];
    const float* src = fb + (long)row * DD;
    float s = 0.f, s2 = 0.f;
    for (int d = tid; d < DD; d += 256) {
        float v = src[d];
        g_fbs[b][f][d] = v * g_c[b][d];
        g_fbT[b][d][f] = v;
        s += v; s2 += v * v;
    }
#pragma unroll
    for (int o = 16; o > 0; o >>= 1) {
        s  += __shfl_xor_sync(0xffffffffu, s, o);
        s2 += __shfl_xor_sync(0xffffffffu, s2, o);
    }
    __shared__ float r1[8], r2[8];
    if ((tid & 31) == 0) { r1[tid >> 5] = s; r2[tid >> 5] = s2; }
    __syncthreads();
    if (tid == 0) {
        float a = 0.f, a2 = 0.f;
#pragma unroll
        for (int i = 0; i < 8; i++) { a += r1[i]; a2 += r2[i]; }
        g_mb[b][f] = a * (1.0f / DD);
        g_mb2[b][f] = a2 * (1.0f / DD);
    }
    const float* wsrc = op + (long)row * (DD * OO);
    for (int i = tid; i < DD * OO; i += 256) {
        int d = i / OO, o = i % OO;
        g_Wb[b][d][f * OO + o] = wsrc[i];
    }
    // Q[b][f][o] = sum_d b_out[d] * wsrc[d*16+o]
    int o = tid & 15, c = tid >> 4;   // 16 chunks x 16 o
    float q = 0.f;
#pragma unroll 4
    for (int i = 0; i < DD / 16; i++) {
        int d = c * (DD / 16) + i;
        q += b_out[d] * wsrc[d * OO + o];
    }
    __shared__ float qs[16][17];
    qs[c][o] = q;
    __syncthreads();
    if (c == 0) {
        float a = 0.f;
#pragma unroll
        for (int i = 0; i < 16; i++) a += qs[i][o];
        g_Q[b][f][o] = a;
    }
}

// ---------------- tiled SGEMM: C = A(MxK) @ B(KxN), row-major, batched by z ----------------
// K % 16 == 0, N % BN == 0 (or at least colBase+BN <= N), float4-aligned pointers.
template <int BM, int BN, int BK, int TM, int TN, int THREADS>
__global__ void __launch_bounds__(THREADS) sgemm(
        const float* __restrict__ Ag, const float* __restrict__ Bg,
        float* __restrict__ Cg, int M, int N, int K,
        long sA, long sB, long sC) {
    const float* A = Ag + (long)blockIdx.z * sA;
    const float* Bp = Bg + (long)blockIdx.z * sB;
    float* C = Cg + (long)blockIdx.z * sC;
    __shared__ float As[BK][BM + 4];
    __shared__ float Bs[BK][BN];
    constexpr int KQ = BK / 4;
    constexpr int N4 = BN / 4;
    constexpr int A4 = BM * KQ;
    constexpr int B4 = BK * N4;
    int tid = threadIdx.x;
    int tc = tid % (BN / TN);
    int tr = tid / (BN / TN);
    int rowBase = blockIdx.y * BM;
    int colBase = blockIdx.x * BN;
    float acc[TM][TN];
#pragma unroll
    for (int i = 0; i < TM; i++)
#pragma unroll
        for (int j = 0; j < TN; j++) acc[i][j] = 0.f;

    for (int k0 = 0; k0 < K; k0 += BK) {
#pragma unroll
        for (int fi = tid; fi < A4; fi += THREADS) {
            int m = fi / KQ, k = (fi % KQ) * 4;
            int gr = rowBase + m;
            float4 v = make_float4(0.f, 0.f, 0.f, 0.f);
            if (gr < M) v = *(const float4*)&A[(long)gr * K + k0 + k];
            As[k + 0][m] = v.x; As[k + 1][m] = v.y; As[k + 2][m] = v.z; As[k + 3][m] = v.w;
        }
#pragma unroll
        for (int fi = tid; fi < B4; fi += THREADS) {
            int kk = fi / N4, nn = (fi % N4) * 4;
            *(float4*)&Bs[kk][nn] = *(const float4*)&Bp[(long)(k0 + kk) * N + colBase + nn];
        }
        __syncthreads();
#pragma unroll
        for (int kk = 0; kk < BK; kk++) {
            float ar[TM], br[TN];
#pragma unroll
            for (int i = 0; i < TM; i += 4)
                *(float4*)&ar[i] = *(const float4*)&As[kk][tr * TM + i];
#pragma unroll
            for (int j = 0; j < TN; j += 4)
                *(float4*)&br[j] = *(const float4*)&Bs[kk][tc * TN + j];
#pragma unroll
            for (int i = 0; i < TM; i++)
#pragma unroll
                for (int j = 0; j < TN; j++) acc[i][j] = fmaf(ar[i], br[j], acc[i][j]);
        }
        __syncthreads();
    }
#pragma unroll
    for (int i = 0; i < TM; i++) {
        int gr = rowBase + tr * TM + i;
        if (gr < M) {
#pragma unroll
            for (int j = 0; j < TN; j += 4) {
                float4 v = make_float4(acc[i][j], acc[i][j + 1], acc[i][j + 2], acc[i][j + 3]);
                *(float4*)&C[(long)gr * N + colBase + tc * TN + j] = v;
            }
        }
    }
}

// ---------------- transpose (R x C) -> (C x R), batched by z ----------------
__global__ void k_transpose(const float* __restrict__ in, float* __restrict__ out, int R, int C) {
    __shared__ float t[32][33];
    long boff = (long)blockIdx.z * R * C;
    int c0 = blockIdx.x * 32, r0 = blockIdx.y * 32;
    int x = c0 + threadIdx.x;
#pragma unroll
    for (int i = threadIdx.y; i < 32; i += 8) {
        int y = r0 + i;
        t[i][threadIdx.x] = in[boff + (long)y * C + x];
    }
    __syncthreads();
    int x2 = r0 + threadIdx.x;
#pragma unroll
    for (int i = threadIdx.y; i < 32; i += 8) {
        int y2 = c0 + i;
        out[boff + (long)y2 * R + x2] = t[threadIdx.x][i];
    }
}

// ---------------- fused main kernel ----------------
// block = (n-tile of 256, f, b); one thread per token. Shared: M_{bf}(64KB), C,d,e (24KB)
__global__ void __launch_bounds__(256) k_main(float* __restrict__ out,
                                              const float* __restrict__ b_in) {
    extern __shared__ float sh[];
    float4* M4 = (float4*)sh;                 // HH*OO floats = HH*4 float4
    float* Csh = sh + HH * OO;                // H2
    float* dsh = Csh + H2;                    // H2
    float* esh = dsh + H2;                    // H2

    int b = blockIdx.z, f = blockIdx.y;
    int n0 = blockIdx.x * 256;
    int t = threadIdx.x;

    for (int i = t; i < HH * 4; i += 256) {
        int j = i >> 2, q = i & 3;
        M4[i] = ((const float4*)(&g_Mm[b][j][f * OO]))[q];
    }
    for (int i = t; i < H2; i += 256) {
        Csh[i] = g_Cf[b][f][i];
        dsh[i] = g_Cf[b][64][i];
        esh[i] = g_Cf[b][65][i] + b_in[i];
    }
    __syncthreads();

    int n = n0 + t;
    float mu = g_mx[b][n] + g_mb[b][f];
    float var = g_mx2[b][n] + 2.0f * g_cr[b][n][f] * (1.0f / DD) + g_mb2[b][f] - mu * mu;
    float rs = rsqrtf(var + EPS);

    float acc[OO];
#pragma unroll
    for (int o = 0; o < OO; o++) acc[o] = 0.f;

    const float* ATg = &g_AT[b][0][0] + n;    // stride NN per j

#pragma unroll 4
    for (int j = 0; j < HH; j++) {
        float aG = ATg[(long)j * NN];
        float aV = ATg[(long)(j + HH) * NN];
        float g = fmaf(rs, aG + Csh[j] - mu * dsh[j], esh[j]);
        float v = fmaf(rs, aV + Csh[j + HH] - mu * dsh[j + HH], esh[j + HH]);
        float sg = __fdividef(1.0f, 1.0f + __expf(-g));
        float z = g * sg * v;
        float4 m0 = M4[j * 4 + 0];
        float4 m1 = M4[j * 4 + 1];
        float4 m2 = M4[j * 4 + 2];
        float4 m3 = M4[j * 4 + 3];
        acc[0]  += z * m0.x; acc[1]  += z * m0.y; acc[2]  += z * m0.z; acc[3]  += z * m0.w;
        acc[4]  += z * m1.x; acc[5]  += z * m1.y; acc[6]  += z * m1.z; acc[7]  += z * m1.w;
        acc[8]  += z * m2.x; acc[9]  += z * m2.y; acc[10] += z * m2.z; acc[11] += z * m2.w;
        acc[12] += z * m3.x; acc[13] += z * m3.y; acc[14] += z * m3.z; acc[15] += z * m3.w;
    }

    long ob = (((long)b * NN + n) * FF + f) * OO;
    const float* Pp = &g_P[b][n][f * OO];
#pragma unroll
    for (int o = 0; o < OO; o++) out[ob + o] = acc[o] + Pp[o] + g_Q[b][f][o];
}

// ---------------- launch ----------------
#define SMEM_MAIN ((HH * OO + 3 * H2) * (int)sizeof(float))

extern "C" void kernel_launch(void* const* d_in, const int* in_sizes, int n_in,
                              void* d_out, int out_size) {
    const float* x     = (const float*)d_in[0];
    const int*   idx   = (const int*)d_in[1];
    const float* ctx   = (const float*)d_in[2];
    const float* fb    = (const float*)d_in[3];
    const float* op    = (const float*)d_in[4];
    const float* ln_w  = (const float*)d_in[5];
    const float* ln_b  = (const float*)d_in[6];
    const float* w_in  = (const float*)d_in[7];
    const float* b_in  = (const float*)d_in[8];
    const float* w_out = (const float*)d_in[9];
    const float* b_out = (const float*)d_in[10];
    float* out = (float*)d_out;

    static bool attr_set = false;
    if (!attr_set) {
        cudaFuncSetAttribute((const void*)k_main, cudaFuncAttributeMaxDynamicSharedMemorySize, SMEM_MAIN);
        attr_set = true;
    }

    float *pXs, *pA, *pAT, *pfbs, *pfbT, *pCf, *pcr, *pWb, *pP, *pM;
    cudaGetSymbolAddress((void**)&pXs,  g_Xs);
    cudaGetSymbolAddress((void**)&pA,   g_A);
    cudaGetSymbolAddress((void**)&pAT,  g_AT);
    cudaGetSymbolAddress((void**)&pfbs, g_fbs);
    cudaGetSymbolAddress((void**)&pfbT, g_fbT);
    cudaGetSymbolAddress((void**)&pCf,  g_Cf);
    cudaGetSymbolAddress((void**)&pcr,  g_cr);
    cudaGetSymbolAddress((void**)&pWb,  g_Wb);
    cudaGetSymbolAddress((void**)&pP,   g_P);
    cudaGetSymbolAddress((void**)&pM,   g_Mm);

    // prep
    k_mod<<<dim3(BB, (2 * DD) / 128), 128>>>(ctx, ln_w, ln_b);
    k_xprep<<<dim3(NN, BB), 128>>>(x);
    k_gather<<<dim3(FF, BB), 256>>>(idx, fb, op, b_out);

    // GEMMs: C = A @ B
    // A_full = Xs @ W_in   (512 x 2048, K=512) per batch
    sgemm<128, 128, 16, 8, 8, 256><<<dim3(H2 / 128, NN / 128, BB), 256>>>(
        pXs, w_in, pA, NN, H2, DD, (long)NN * DD, 0, (long)NN * H2);
    // transpose A -> AT
    k_transpose<<<dim3(H2 / 32, NN / 32, BB), dim3(32, 8)>>>(pA, pAT, NN, H2);
    // Cf_ext = fbs_ext @ W_in   (66 x 2048, K=512); rows 64/65 produce d and e_raw
    sgemm<128, 128, 16, 8, 8, 256><<<dim3(H2 / 128, 1, BB), 256>>>(
        pfbs, w_in, pCf, FBM, H2, DD, (long)FBM * DD, 0, (long)FBM * H2);
    // cr = X @ fbT      (512 x 64, K=512)
    sgemm<64, 64, 16, 4, 4, 256><<<dim3(1, NN / 64, BB), 256>>>(
        x, pfbT, pcr, NN, FF, DD, (long)NN * DD, (long)DD * FF, (long)NN * FF);
    // P = X @ Wb        (512 x 1024, K=512)
    sgemm<128, 64, 16, 8, 4, 256><<<dim3(FO / 64, NN / 128, BB), 256>>>(
        x, pWb, pP, NN, FO, DD, (long)NN * DD, (long)DD * FO, (long)NN * FO);
    // Mm = W_out @ Wb   (1024 x 1024, K=512)
    sgemm<128, 128, 16, 8, 8, 256><<<dim3(FO / 128, HH / 128, BB), 256>>>(
        w_out, pWb, pM, HH, FO, DD, 0, (long)DD * FO, (long)HH * FO);

    // fused main
    k_main<<<dim3(NN / 256, FF, BB), 256, SMEM_MAIN>>>(out, b_in);
}